// round 2
// baseline (speedup 1.0000x reference)
#include <cuda_runtime.h>
#include <cstdint>

#define N_PTS     16384
#define NQ_TILE   1024      // queries per block
#define NT_SPLIT  256       // targets per block
#define RA        8         // queries per thread
#define THREADS   128       // NQ_TILE / RA
#define N_SPLITS  (N_PTS / NT_SPLIT)   // 64
#define N_QTILES  (N_PTS / NQ_TILE)    // 16
#define MAIN_BLOCKS (2 * N_QTILES * N_SPLITS)  // 2048

#define RED_THREADS 1024
#define RED_BLOCKS  (2 * N_PTS / RED_THREADS)  // 32

typedef unsigned long long u64;

// Precomputed target-side SoA: set 0 = gen points, set 1 = gt points.
// X/Y/Z are scaled by -2; C = |p|^2.
__device__ float g_TX[2][N_PTS];
__device__ float g_TY[2][N_PTS];
__device__ float g_TZ[2][N_PTS];
__device__ float g_TC[2][N_PTS];

// Per-split partial mins in "e-space" (e = c_b - 2 a.b), row index = split,
// col index = dir*N_PTS + query. Every slot is written each run -> no init.
__device__ float g_minpart[N_SPLITS][2 * N_PTS];

// Block partial sums for the final reduction.
__device__ float g_partial[RED_BLOCKS];

// ---------------- f32x2 helpers ----------------
__device__ __forceinline__ u64 pack2(float a, float b) {
    u64 r;
    asm("mov.b64 %0, {%1, %2};" : "=l"(r) : "f"(a), "f"(b));
    return r;
}
__device__ __forceinline__ u64 fma2(u64 a, u64 b, u64 c) {
    u64 d;
    asm("fma.rn.f32x2 %0, %1, %2, %3;" : "=l"(d) : "l"(a), "l"(b), "l"(c));
    return d;
}
__device__ __forceinline__ void unpack2(u64 v, float& lo, float& hi) {
    asm("mov.b64 {%0, %1}, %2;" : "=f"(lo), "=f"(hi) : "l"(v));
}

// ---------------- Kernel 1: precompute target SoA ----------------
__global__ void precompute_kernel(const float* __restrict__ gt,
                                  const float* __restrict__ gen) {
    int i = blockIdx.x * blockDim.x + threadIdx.x;   // 0 .. 2*N_PTS-1
    if (i >= 2 * N_PTS) return;
    int s = i >> 14;          // 0: gen, 1: gt
    int j = i & (N_PTS - 1);
    const float* p = s ? gt : gen;
    float x = p[3 * j + 0];
    float y = p[3 * j + 1];
    float z = p[3 * j + 2];
    g_TX[s][j] = -2.0f * x;
    g_TY[s][j] = -2.0f * y;
    g_TZ[s][j] = -2.0f * z;
    g_TC[s][j] = x * x + y * y + z * z;
}

// ---------------- Kernel 2: main pairwise min ----------------
// Block = (dir, qtile, split). Each thread owns RA=8 queries and scans the
// split's 256 targets held in shared memory (loaded as packed float pairs).
__global__ __launch_bounds__(THREADS) void chamfer_main_kernel(
    const float* __restrict__ gt, const float* __restrict__ gen) {

    __shared__ u64 sX[NT_SPLIT / 2];
    __shared__ u64 sY[NT_SPLIT / 2];
    __shared__ u64 sZ[NT_SPLIT / 2];
    __shared__ u64 sC[NT_SPLIT / 2];

    const int b     = blockIdx.x;
    const int dir   = b / (N_QTILES * N_SPLITS);     // 0: gt->gen, 1: gen->gt
    const int rem   = b % (N_QTILES * N_SPLITS);
    const int qtile = rem / N_SPLITS;
    const int split = rem % N_SPLITS;

    const int ts = (dir == 0) ? 0 : 1;               // target set
    const float* qpts = (dir == 0) ? gt : gen;       // raw query points

    const int tid = threadIdx.x;

    // Stage target split into shared (packed pairs). 256 targets -> 128 u64 per array.
    {
        const int tbase = split * NT_SPLIT;
        const float2* gx = reinterpret_cast<const float2*>(&g_TX[ts][tbase]);
        const float2* gy = reinterpret_cast<const float2*>(&g_TY[ts][tbase]);
        const float2* gz = reinterpret_cast<const float2*>(&g_TZ[ts][tbase]);
        const float2* gc = reinterpret_cast<const float2*>(&g_TC[ts][tbase]);
        if (tid < NT_SPLIT / 2) {
            float2 vx = gx[tid], vy = gy[tid], vz = gz[tid], vc = gc[tid];
            sX[tid] = pack2(vx.x, vx.y);
            sY[tid] = pack2(vy.x, vy.y);
            sZ[tid] = pack2(vz.x, vz.y);
            sC[tid] = pack2(vc.x, vc.y);
        }
    }

    // Load this thread's RA queries (replicated into both f32x2 halves).
    u64 ax2[RA], ay2[RA], az2[RA];
    const int qbase = qtile * NQ_TILE;
#pragma unroll
    for (int r = 0; r < RA; r++) {
        int q = qbase + tid + r * THREADS;
        float x = qpts[3 * q + 0];
        float y = qpts[3 * q + 1];
        float z = qpts[3 * q + 2];
        ax2[r] = pack2(x, x);
        ay2[r] = pack2(y, y);
        az2[r] = pack2(z, z);
    }

    float rm[RA];
#pragma unroll
    for (int r = 0; r < RA; r++) rm[r] = 3.4e38f;

    __syncthreads();

    // Main loop: 128 packed target pairs x 8 queries = 2048 pairs per thread.
#pragma unroll 4
    for (int t = 0; t < NT_SPLIT / 2; t++) {
        u64 bx2 = sX[t];
        u64 by2 = sY[t];
        u64 bz2 = sZ[t];
        u64 bc2 = sC[t];
#pragma unroll
        for (int r = 0; r < RA; r++) {
            u64 acc = fma2(az2[r], bz2, bc2);
            acc = fma2(ay2[r], by2, acc);
            acc = fma2(ax2[r], bx2, acc);
            float lo, hi;
            unpack2(acc, lo, hi);
            rm[r] = fminf(rm[r], fminf(lo, hi));
        }
    }

    // Write per-(query, split) partial mins; coalesced per r.
    float* dst = &g_minpart[split][dir * N_PTS + qbase];
#pragma unroll
    for (int r = 0; r < RA; r++) {
        dst[tid + r * THREADS] = rm[r];
    }
}

// ---------------- Kernel 3: min over splits + |a|^2 fold + block sums ----------------
__global__ __launch_bounds__(RED_THREADS) void reduce_kernel() {
    const int i = blockIdx.x * RED_THREADS + threadIdx.x;  // 0 .. 2*N_PTS-1

    float m = g_minpart[0][i];
#pragma unroll 8
    for (int s = 1; s < N_SPLITS; s++) {
        m = fminf(m, g_minpart[s][i]);
    }
    // Fold the query's |a|^2: dir0 queries are gt (set 1), dir1 queries are gen (set 0).
    int dir = i >> 14;
    int q   = i & (N_PTS - 1);
    float ca = (dir == 0) ? g_TC[1][q] : g_TC[0][q];
    float val = ca + m;

    // Block sum reduction.
    __shared__ float ssum[RED_THREADS / 32];
    float v = val;
#pragma unroll
    for (int off = 16; off > 0; off >>= 1)
        v += __shfl_xor_sync(0xFFFFFFFFu, v, off);
    int lane = threadIdx.x & 31;
    int wid  = threadIdx.x >> 5;
    if (lane == 0) ssum[wid] = v;
    __syncthreads();
    if (wid == 0) {
        float w = (lane < RED_THREADS / 32) ? ssum[lane] : 0.0f;
#pragma unroll
        for (int off = 16; off > 0; off >>= 1)
            w += __shfl_xor_sync(0xFFFFFFFFu, w, off);
        if (lane == 0) g_partial[blockIdx.x] = w;
    }
}

// ---------------- Kernel 4: final scalar ----------------
__global__ void final_kernel(float* __restrict__ out) {
    float v = (threadIdx.x < RED_BLOCKS) ? g_partial[threadIdx.x] : 0.0f;
#pragma unroll
    for (int off = 16; off > 0; off >>= 1)
        v += __shfl_xor_sync(0xFFFFFFFFu, v, off);
    if (threadIdx.x == 0)
        out[0] = v * (1.0f / (float)N_PTS);
}

// ---------------- launch ----------------
extern "C" void kernel_launch(void* const* d_in, const int* in_sizes, int n_in,
                              void* d_out, int out_size) {
    const float* gt  = (const float*)d_in[0];
    const float* gen = (const float*)d_in[1];
    float* out = (float*)d_out;

    precompute_kernel<<<(2 * N_PTS + 255) / 256, 256>>>(gt, gen);
    chamfer_main_kernel<<<MAIN_BLOCKS, THREADS>>>(gt, gen);
    reduce_kernel<<<RED_BLOCKS, RED_THREADS>>>();
    final_kernel<<<1, 32>>>(out);
}